// round 11
// baseline (speedup 1.0000x reference)
#include <cuda_runtime.h>

#define NQ 12
#define NS 4096
#define TPB 256
#define NL 3

__device__ float g_gates[NL * NQ * 8];
__device__ float g_Q[16];   // readout Hermitian form (diag d0..d3, then 6 pre-doubled complex off-diags)

__global__ void prep_gates(const float* __restrict__ params, const float* __restrict__ head_w) {
    int t = blockIdx.x * blockDim.x + threadIdx.x;
    if (t < NL * NQ) {
        float t0 = params[t * 3 + 0], t1 = params[t * 3 + 1], t2 = params[t * 3 + 2];
        float c0 = cosf(0.5f * t0), s0 = sinf(0.5f * t0);
        float cp = cosf(0.5f * t1), sp = sinf(0.5f * t1);
        float c2 = cosf(0.5f * t2), s2 = sinf(0.5f * t2);
        float A_re = cp * c0, A_im = -sp * c0;
        float B_re = -cp * s0, B_im = sp * s0;
        float C_re = cp * s0, C_im = sp * s0;
        float D_re = cp * c0, D_im = sp * c0;
        float* g = &g_gates[t * 8];
        g[0] = c2 * A_re - s2 * C_re;  g[1] = c2 * A_im - s2 * C_im;
        g[2] = c2 * B_re - s2 * D_re;  g[3] = c2 * B_im - s2 * D_im;
        g[4] = s2 * A_re + c2 * C_re;  g[5] = s2 * A_im + c2 * C_im;
        g[6] = s2 * B_re + c2 * D_re;  g[7] = s2 * B_im + c2 * D_im;
    }
    __syncthreads();
    if (t == 0) {
        // H = G^dag Z G for last-layer gates 10, 11
        const float* ga = &g_gates[((NL - 1) * NQ + 10) * 8];
        const float* gb = &g_gates[((NL - 1) * NQ + 11) * 8];
        float A00 = ga[0]*ga[0] + ga[1]*ga[1] - (ga[4]*ga[4] + ga[5]*ga[5]);
        float A11 = ga[2]*ga[2] + ga[3]*ga[3] - (ga[6]*ga[6] + ga[7]*ga[7]);
        float A01x = ga[0]*ga[2] + ga[1]*ga[3] - (ga[4]*ga[6] + ga[5]*ga[7]);
        float A01y = ga[0]*ga[3] - ga[1]*ga[2] - (ga[4]*ga[7] - ga[5]*ga[6]);
        float B00 = gb[0]*gb[0] + gb[1]*gb[1] - (gb[4]*gb[4] + gb[5]*gb[5]);
        float B11 = gb[2]*gb[2] + gb[3]*gb[3] - (gb[6]*gb[6] + gb[7]*gb[7]);
        float B01x = gb[0]*gb[2] + gb[1]*gb[3] - (gb[4]*gb[6] + gb[5]*gb[7]);
        float B01y = gb[0]*gb[3] - gb[1]*gb[2] - (gb[4]*gb[7] - gb[5]*gb[6]);
        float w10 = head_w[10], w11 = head_w[11];
        float cA = w10 + w11 * B00;
        float cB = w10 + w11 * B11;
        g_Q[0] = A00 * cA;
        g_Q[1] = A00 * cB;
        g_Q[2] = A11 * cA;
        g_Q[3] = A11 * cB;
        g_Q[4] = 2.f * w11 * A00 * B01x;  g_Q[5] = 2.f * w11 * A00 * B01y;
        g_Q[6] = 2.f * A01x * cA;         g_Q[7] = 2.f * A01y * cA;
        g_Q[8]  = 2.f * w11 * (A01x*B01x - A01y*B01y);
        g_Q[9]  = 2.f * w11 * (A01x*B01y + A01y*B01x);
        g_Q[10] = 2.f * w11 * (A01x*B01x + A01y*B01y);
        g_Q[11] = 2.f * w11 * (A01y*B01x - A01x*B01y);
        g_Q[12] = 2.f * A01x * cB;        g_Q[13] = 2.f * A01y * cB;
        g_Q[14] = 2.f * w11 * A11 * B01x; g_Q[15] = 2.f * w11 * A11 * B01y;
    }
}

struct G2 { float2 g00, g01, g10, g11; };

__device__ __forceinline__ float2 cmul(float2 a, float2 b) {
    return make_float2(a.x * b.x - a.y * b.y, a.x * b.y + a.y * b.x);
}

__device__ __forceinline__ void apply_pair(const G2& g, float2& a, float2& b) {
    float2 na, nb;
    na.x = g.g00.x * a.x - g.g00.y * a.y + g.g01.x * b.x - g.g01.y * b.y;
    na.y = g.g00.x * a.y + g.g00.y * a.x + g.g01.x * b.y + g.g01.y * b.x;
    nb.x = g.g10.x * a.x - g.g10.y * a.y + g.g11.x * b.x - g.g11.y * b.y;
    nb.y = g.g10.x * a.y + g.g10.y * a.x + g.g11.x * b.y + g.g11.y * b.x;
    a = na; b = nb;
}

__device__ __forceinline__ G2 load_gate(const float4* gsm4, int l, int w) {
    float4 p0 = gsm4[(l * NQ + w) * 2 + 0];
    float4 p1 = gsm4[(l * NQ + w) * 2 + 1];
    G2 r;
    r.g00 = make_float2(p0.x, p0.y);
    r.g01 = make_float2(p0.z, p0.w);
    r.g10 = make_float2(p1.x, p1.y);
    r.g11 = make_float2(p1.z, p1.w);
    return r;
}

__device__ __forceinline__ void gate_on_bit(const G2& g, float2 r[16], int k) {
    #pragma unroll
    for (int l = 0; l < 16; l++)
        if (!(l & (1 << k))) apply_pair(g, r[l], r[l | (1 << k)]);
}

__device__ __forceinline__ void cnot_loc(float2 r[16], int c, int tg) {
    #pragma unroll
    for (int l = 0; l < 16; l++)
        if ((l & (1 << c)) && !(l & (1 << tg))) {
            float2 tmp = r[l]; r[l] = r[l | (1 << tg)]; r[l | (1 << tg)] = tmp;
        }
}

// Stage maps (verified). t = thread (8 bits), l = local (4 bits).
// Warp id (t>>5) == g[11:9] in S1, S2, S3 -> each transpose crosses warps on
// at most ONE side, so a single shared buffer with W -> bar -> R is safe.
__device__ __forceinline__ int gS0(int t, int l) { return (l << 8) | t; }
__device__ __forceinline__ int gS1(int t, int l) { return ((t >> 5) << 9) | (l << 5) | (t & 31); }
__device__ __forceinline__ int gS2(int t, int l) { return ((t >> 5) << 9) | (((t >> 2) & 7) << 6) | (l << 2) | (t & 3); }
__device__ __forceinline__ int gS3(int t, int l) { return ((t >> 5) << 9) | ((t & 31) << 4) | l; }
__device__ __forceinline__ int swz(int g, int m) { return g ^ ((g >> 4) & m); }

__global__ __launch_bounds__(TPB, 4) void qsim(
    const float* __restrict__ x, const float* __restrict__ head_w,
    const float* __restrict__ head_b, float* __restrict__ out) {
    extern __shared__ float2 st[];             // single 32 KB transpose buffer
    __shared__ float4 gsm4[NL * NQ * 2];
    __shared__ float2 vsm[NQ][2];
    __shared__ float qsm[16];
    __shared__ float wred[TPB / 32];

    int b = blockIdx.x, t = threadIdx.x;

    {
        float* gsm = (float*)gsm4;
        for (int i = t; i < NL * NQ * 8; i += TPB) gsm[i] = g_gates[i];
    }
    if (t < 16) qsm[t] = g_Q[t];
    if (t < NQ) {
        // v_w = G_{layer0,w} @ [cos(x/2), -i sin(x/2)]
        float xv = x[b * NQ + t];
        float c = cosf(0.5f * xv), s = sinf(0.5f * xv);
        const float* g = &g_gates[t * 8];
        vsm[t][0] = make_float2(g[0] * c + s * g[3], g[1] * c - s * g[2]);
        vsm[t][1] = make_float2(g[4] * c + s * g[7], g[5] * c - s * g[6]);
    }
    __syncthreads();

    float2 r[16];

    // --- Init in S0 layout, layer-1 gates + CNOT chain absorbed ---
    {
        int u = t ^ (t >> 1);
        float2 P = vsm[5][(u >> 6) & 1];
        #pragma unroll
        for (int w = 6; w < NQ; w++) P = cmul(P, vsm[w][(u >> (11 - w)) & 1]);
        int t7 = (t >> 7) & 1;
        float2 W34[4];
        #pragma unroll
        for (int j = 0; j < 4; j++) {
            int l1 = j >> 1, l0 = j & 1;
            W34[j] = cmul(cmul(vsm[3][l1 ^ l0], vsm[4][t7 ^ l0]), P);
        }
        float2 W012[8];
        #pragma unroll
        for (int k = 0; k < 8; k++) {
            int l3 = k >> 2, l2 = (k >> 1) & 1, l1 = k & 1;
            W012[k] = cmul(cmul(vsm[0][l3], vsm[1][l3 ^ l2]), vsm[2][l2 ^ l1]);
        }
        #pragma unroll
        for (int l = 0; l < 16; l++)
            r[l] = cmul(W012[l >> 1], W34[l & 3]);
    }

    // Single-buffer transposes.
    // XPOSE (CTA-wide side): write -> syncthreads -> read.
    #define XPOSE(GSRC, GDST, MASK) do {                                    \
        _Pragma("unroll")                                                   \
        for (int i_ = 0; i_ < 16; i_++) st[swz(GSRC(t, i_), MASK)] = r[i_]; \
        __syncthreads();                                                    \
        _Pragma("unroll")                                                   \
        for (int i_ = 0; i_ < 16; i_++) r[i_] = st[swz(GDST(t, i_), MASK)]; \
    } while (0)

    // Warp-local (both sides stay in the warp's 512-amp block).
    #define XPOSE_W(GSRC, GDST, MASK) do {                                  \
        _Pragma("unroll")                                                   \
        for (int i_ = 0; i_ < 16; i_++) st[swz(GSRC(t, i_), MASK)] = r[i_]; \
        __syncwarp();                                                       \
        _Pragma("unroll")                                                   \
        for (int i_ = 0; i_ < 16; i_++) r[i_] = st[swz(GDST(t, i_), MASK)]; \
    } while (0)

    #pragma unroll
    for (int l = 1; l < NL; l++) {
        // S0: wires 0-3 (lowest local bit first; pre-chain gates commute)
        {
            G2 G3 = load_gate(gsm4, l, 3);  gate_on_bit(G3, r, 0);
            G2 Gc = load_gate(gsm4, l, 2);  gate_on_bit(Gc, r, 1);
            G2 G1 = load_gate(gsm4, l, 1);  gate_on_bit(G1, r, 2);
            G2 G0 = load_gate(gsm4, l, 0);  gate_on_bit(G0, r, 3);
            cnot_loc(r, 3, 2); cnot_loc(r, 2, 1); cnot_loc(r, 1, 0);
        }
        // Layer >1: the S0->S1 write crosses warps and follows the previous
        // layer's cross-warp S3->S0 read -> WAR hazard, one extra barrier.
        if (l > 1) __syncthreads();
        XPOSE(gS0, gS1, 0);
        // S1: wires 3..6; gates 4,5,6
        {
            G2 G6 = load_gate(gsm4, l, 6); gate_on_bit(G6, r, 0);
            G2 G5 = load_gate(gsm4, l, 5); gate_on_bit(G5, r, 1);
            G2 G4 = load_gate(gsm4, l, 4); gate_on_bit(G4, r, 2);
            cnot_loc(r, 3, 2); cnot_loc(r, 2, 1); cnot_loc(r, 1, 0);
        }
        XPOSE_W(gS1, gS2, 0xC);
        // S2: wires 6..9; gates 7,8,9
        {
            G2 G9 = load_gate(gsm4, l, 9); gate_on_bit(G9, r, 0);
            G2 G8 = load_gate(gsm4, l, 8); gate_on_bit(G8, r, 1);
            G2 G7 = load_gate(gsm4, l, 7); gate_on_bit(G7, r, 2);
            cnot_loc(r, 3, 2); cnot_loc(r, 2, 1); cnot_loc(r, 1, 0);
        }
        XPOSE_W(gS2, gS3, 0xF);
        // S3: wires 8..11; gates 10,11 + CNOTs (9,10),(10,11) — only for the
        // middle layer; last layer absorbed into Q-form readout.
        if (l < NL - 1) {
            G2 Gb = load_gate(gsm4, l, 11); gate_on_bit(Gb, r, 0);
            G2 Ga = load_gate(gsm4, l, 10); gate_on_bit(Ga, r, 1);
            cnot_loc(r, 2, 1); cnot_loc(r, 1, 0);
            // S3 write is warp-local (warp id == g[11:9]); read crosses warps.
            XPOSE(gS3, gS0, 0xF);
        }
    }

    // --- Readout in S3 layout: wires 8(l3),9(l2),10(l1),11(l0) ---
    float swt = 0.f;
    {
        int g = gS3(t, 0);
        #pragma unroll
        for (int w = 0; w < 8; w++)
            swt += ((g >> (11 - w)) & 1) ? -head_w[w] : head_w[w];
    }
    float w8 = head_w[8], w9 = head_w[9];
    float acc = 0.f;
    #pragma unroll
    for (int g2 = 0; g2 < 4; g2++) {
        int l3 = g2 >> 1, l2 = g2 & 1;
        float2 z0 = r[g2 * 4 + 0], z1 = r[g2 * 4 + 1];
        float2 z2 = r[g2 * 4 + 2], z3 = r[g2 * 4 + 3];
        float P0 = z0.x*z0.x + z0.y*z0.y;
        float P1 = z1.x*z1.x + z1.y*z1.y;
        float P2 = z2.x*z2.x + z2.y*z2.y;
        float P3 = z3.x*z3.x + z3.y*z3.y;
        float A9 = swt + (l3 ? -w8 : w8) + (l2 ? -w9 : w9);
        float q = qsm[0]*P0 + qsm[1]*P1 + qsm[2]*P2 + qsm[3]*P3;
        float X, Y;
        X = z0.x*z1.x + z0.y*z1.y;  Y = z0.x*z1.y - z0.y*z1.x;  q += qsm[4]*X  - qsm[5]*Y;
        X = z0.x*z2.x + z0.y*z2.y;  Y = z0.x*z2.y - z0.y*z2.x;  q += qsm[6]*X  - qsm[7]*Y;
        X = z0.x*z3.x + z0.y*z3.y;  Y = z0.x*z3.y - z0.y*z3.x;  q += qsm[8]*X  - qsm[9]*Y;
        X = z1.x*z2.x + z1.y*z2.y;  Y = z1.x*z2.y - z1.y*z2.x;  q += qsm[10]*X - qsm[11]*Y;
        X = z1.x*z3.x + z1.y*z3.y;  Y = z1.x*z3.y - z1.y*z3.x;  q += qsm[12]*X - qsm[13]*Y;
        X = z2.x*z3.x + z2.y*z3.y;  Y = z2.x*z3.y - z2.y*z3.x;  q += qsm[14]*X - qsm[15]*Y;
        float sumP = (P0 + P1) + (P2 + P3);
        acc = fmaf(sumP, A9, acc);
        acc += l2 ? -q : q;
    }
    #pragma unroll
    for (int o = 16; o > 0; o >>= 1) acc += __shfl_xor_sync(0xFFFFFFFFu, acc, o);
    if ((t & 31) == 0) wred[t >> 5] = acc;
    __syncthreads();
    if (t == 0) {
        float tot = 0.f;
        #pragma unroll
        for (int i = 0; i < TPB / 32; i++) tot += wred[i];
        out[b] = tot + head_b[0];
    }
}

#define DYN_SMEM (NS * sizeof(float2))

extern "C" void kernel_launch(void* const* d_in, const int* in_sizes, int n_in,
                              void* d_out, int out_size) {
    const float* x      = (const float*)d_in[0];
    const float* params = (const float*)d_in[1];
    const float* head_w = (const float*)d_in[2];
    const float* head_b = (const float*)d_in[3];
    float* out = (float*)d_out;
    int B = in_sizes[0] / NQ;
    static int smem_set = 0;
    if (!smem_set) {
        cudaFuncSetAttribute(qsim, cudaFuncAttributeMaxDynamicSharedMemorySize, DYN_SMEM);
        smem_set = 1;
    }
    prep_gates<<<1, 64>>>(params, head_w);
    qsim<<<B, TPB, DYN_SMEM>>>(x, head_w, head_b, out);
}

// round 12
// speedup vs baseline: 1.0497x; 1.0497x over previous
#include <cuda_runtime.h>

#define NQ 12
#define NS 4096
#define TPB 256
#define NL 3

__device__ float g_gates[NL * NQ * 8];
__device__ float g_Q[16];    // readout Hermitian form
__device__ float g_swt[256]; // per-thread sign-sum over wires 0..7 (index == tid)

__global__ void prep_gates(const float* __restrict__ params, const float* __restrict__ head_w) {
    int t = blockIdx.x * blockDim.x + threadIdx.x;
    if (t < NL * NQ) {
        float t0 = params[t * 3 + 0], t1 = params[t * 3 + 1], t2 = params[t * 3 + 2];
        float c0 = cosf(0.5f * t0), s0 = sinf(0.5f * t0);
        float cp = cosf(0.5f * t1), sp = sinf(0.5f * t1);
        float c2 = cosf(0.5f * t2), s2 = sinf(0.5f * t2);
        float A_re = cp * c0, A_im = -sp * c0;
        float B_re = -cp * s0, B_im = sp * s0;
        float C_re = cp * s0, C_im = sp * s0;
        float D_re = cp * c0, D_im = sp * c0;
        float* g = &g_gates[t * 8];
        g[0] = c2 * A_re - s2 * C_re;  g[1] = c2 * A_im - s2 * C_im;
        g[2] = c2 * B_re - s2 * D_re;  g[3] = c2 * B_im - s2 * D_im;
        g[4] = s2 * A_re + c2 * C_re;  g[5] = s2 * A_im + c2 * C_im;
        g[6] = s2 * B_re + c2 * D_re;  g[7] = s2 * B_im + c2 * D_im;
    }
    // swt table: for thread id t, g = gS3(t,0) has (g>>4)&0xFF == t, and wire w
    // (w<8) reads bit (7-w) of that byte. tab[t] = sum_w +-head_w[w].
    if (t < 256) {
        float s = 0.f;
        for (int w = 0; w < 8; w++)
            s += ((t >> (7 - w)) & 1) ? -head_w[w] : head_w[w];
        g_swt[t] = s;
    }
    __syncthreads();
    if (t == 0) {
        // H = G^dag Z G for last-layer gates 10, 11
        const float* ga = &g_gates[((NL - 1) * NQ + 10) * 8];
        const float* gb = &g_gates[((NL - 1) * NQ + 11) * 8];
        float A00 = ga[0]*ga[0] + ga[1]*ga[1] - (ga[4]*ga[4] + ga[5]*ga[5]);
        float A11 = ga[2]*ga[2] + ga[3]*ga[3] - (ga[6]*ga[6] + ga[7]*ga[7]);
        float A01x = ga[0]*ga[2] + ga[1]*ga[3] - (ga[4]*ga[6] + ga[5]*ga[7]);
        float A01y = ga[0]*ga[3] - ga[1]*ga[2] - (ga[4]*ga[7] - ga[5]*ga[6]);
        float B00 = gb[0]*gb[0] + gb[1]*gb[1] - (gb[4]*gb[4] + gb[5]*gb[5]);
        float B11 = gb[2]*gb[2] + gb[3]*gb[3] - (gb[6]*gb[6] + gb[7]*gb[7]);
        float B01x = gb[0]*gb[2] + gb[1]*gb[3] - (gb[4]*gb[6] + gb[5]*gb[7]);
        float B01y = gb[0]*gb[3] - gb[1]*gb[2] - (gb[4]*gb[7] - gb[5]*gb[6]);
        float w10 = head_w[10], w11 = head_w[11];
        float cA = w10 + w11 * B00;
        float cB = w10 + w11 * B11;
        g_Q[0] = A00 * cA;
        g_Q[1] = A00 * cB;
        g_Q[2] = A11 * cA;
        g_Q[3] = A11 * cB;
        g_Q[4] = 2.f * w11 * A00 * B01x;  g_Q[5] = 2.f * w11 * A00 * B01y;
        g_Q[6] = 2.f * A01x * cA;         g_Q[7] = 2.f * A01y * cA;
        g_Q[8]  = 2.f * w11 * (A01x*B01x - A01y*B01y);
        g_Q[9]  = 2.f * w11 * (A01x*B01y + A01y*B01x);
        g_Q[10] = 2.f * w11 * (A01x*B01x + A01y*B01y);
        g_Q[11] = 2.f * w11 * (A01y*B01x - A01x*B01y);
        g_Q[12] = 2.f * A01x * cB;        g_Q[13] = 2.f * A01y * cB;
        g_Q[14] = 2.f * w11 * A11 * B01x; g_Q[15] = 2.f * w11 * A11 * B01y;
    }
}

struct G2 { float2 g00, g01, g10, g11; };

__device__ __forceinline__ float2 cmul(float2 a, float2 b) {
    return make_float2(a.x * b.x - a.y * b.y, a.x * b.y + a.y * b.x);
}

__device__ __forceinline__ void apply_pair(const G2& g, float2& a, float2& b) {
    float2 na, nb;
    na.x = g.g00.x * a.x - g.g00.y * a.y + g.g01.x * b.x - g.g01.y * b.y;
    na.y = g.g00.x * a.y + g.g00.y * a.x + g.g01.x * b.y + g.g01.y * b.x;
    nb.x = g.g10.x * a.x - g.g10.y * a.y + g.g11.x * b.x - g.g11.y * b.y;
    nb.y = g.g10.x * a.y + g.g10.y * a.x + g.g11.x * b.y + g.g11.y * b.x;
    a = na; b = nb;
}

__device__ __forceinline__ G2 load_gate(const float4* gsm4, int l, int w) {
    float4 p0 = gsm4[(l * NQ + w) * 2 + 0];
    float4 p1 = gsm4[(l * NQ + w) * 2 + 1];
    G2 r;
    r.g00 = make_float2(p0.x, p0.y);
    r.g01 = make_float2(p0.z, p0.w);
    r.g10 = make_float2(p1.x, p1.y);
    r.g11 = make_float2(p1.z, p1.w);
    return r;
}

__device__ __forceinline__ void gate_on_bit(const G2& g, float2 r[16], int k) {
    #pragma unroll
    for (int l = 0; l < 16; l++)
        if (!(l & (1 << k))) apply_pair(g, r[l], r[l | (1 << k)]);
}

__device__ __forceinline__ void cnot_loc(float2 r[16], int c, int tg) {
    #pragma unroll
    for (int l = 0; l < 16; l++)
        if ((l & (1 << c)) && !(l & (1 << tg))) {
            float2 tmp = r[l]; r[l] = r[l | (1 << tg)]; r[l | (1 << tg)] = tmp;
        }
}

// Stage maps (verified). t = thread (8 bits), l = local (4 bits).
__device__ __forceinline__ int gS0(int t, int l) { return (l << 8) | t; }
__device__ __forceinline__ int gS1(int t, int l) { return ((t >> 5) << 9) | (l << 5) | (t & 31); }
__device__ __forceinline__ int gS2(int t, int l) { return ((t >> 5) << 9) | (((t >> 2) & 7) << 6) | (l << 2) | (t & 3); }
__device__ __forceinline__ int gS3(int t, int l) { return ((t >> 5) << 9) | ((t & 31) << 4) | l; }
__device__ __forceinline__ int swz(int g, int m) { return g ^ ((g >> 4) & m); }

__global__ __launch_bounds__(TPB, 3) void qsim(
    const float* __restrict__ x, const float* __restrict__ head_w,
    const float* __restrict__ head_b, float* __restrict__ out) {
    extern __shared__ float2 stbuf[];          // 2 * 4096 float2 = 64 KB (double buffer)
    float2* st0 = stbuf;
    float2* st1 = stbuf + NS;
    __shared__ float4 gsm4[NL * NQ * 2];
    __shared__ float2 vsm[NQ][2];
    __shared__ float qsm[16];
    __shared__ float swtab[256];
    __shared__ float wred[TPB / 32];

    int b = blockIdx.x, t = threadIdx.x;

    {
        float* gsm = (float*)gsm4;
        for (int i = t; i < NL * NQ * 8; i += TPB) gsm[i] = g_gates[i];
    }
    swtab[t] = g_swt[t];
    if (t < 16) qsm[t] = g_Q[t];
    if (t < NQ) {
        // v_w = G_{layer0,w} @ [cos(x/2), -i sin(x/2)]
        float xv = x[b * NQ + t];
        float c = cosf(0.5f * xv), s = sinf(0.5f * xv);
        const float* g = &g_gates[t * 8];
        vsm[t][0] = make_float2(g[0] * c + s * g[3], g[1] * c - s * g[2]);
        vsm[t][1] = make_float2(g[4] * c + s * g[7], g[5] * c - s * g[6]);
    }
    __syncthreads();

    float2 r[16];

    // --- Init in S0 layout, layer-1 gates + CNOT chain absorbed ---
    {
        int u = t ^ (t >> 1);
        float2 P = vsm[5][(u >> 6) & 1];
        #pragma unroll
        for (int w = 6; w < NQ; w++) P = cmul(P, vsm[w][(u >> (11 - w)) & 1]);
        int t7 = (t >> 7) & 1;
        float2 W34[4];
        #pragma unroll
        for (int j = 0; j < 4; j++) {
            int l1 = j >> 1, l0 = j & 1;
            W34[j] = cmul(cmul(vsm[3][l1 ^ l0], vsm[4][t7 ^ l0]), P);
        }
        float2 W012[8];
        #pragma unroll
        for (int k = 0; k < 8; k++) {
            int l3 = k >> 2, l2 = (k >> 1) & 1, l1 = k & 1;
            W012[k] = cmul(cmul(vsm[0][l3], vsm[1][l3 ^ l2]), vsm[2][l2 ^ l1]);
        }
        #pragma unroll
        for (int l = 0; l < 16; l++)
            r[l] = cmul(W012[l >> 1], W34[l & 3]);
    }

    #define XPOSE(BUF, GSRC, GDST, MASK) do {                               \
        _Pragma("unroll")                                                   \
        for (int i_ = 0; i_ < 16; i_++) BUF[swz(GSRC(t, i_), MASK)] = r[i_]; \
        __syncthreads();                                                    \
        _Pragma("unroll")                                                   \
        for (int i_ = 0; i_ < 16; i_++) r[i_] = BUF[swz(GDST(t, i_), MASK)]; \
    } while (0)

    #define XPOSE_W(BUF, GSRC, GDST, MASK) do {                             \
        _Pragma("unroll")                                                   \
        for (int i_ = 0; i_ < 16; i_++) BUF[swz(GSRC(t, i_), MASK)] = r[i_]; \
        __syncwarp();                                                       \
        _Pragma("unroll")                                                   \
        for (int i_ = 0; i_ < 16; i_++) r[i_] = BUF[swz(GDST(t, i_), MASK)]; \
    } while (0)

    #pragma unroll
    for (int l = 1; l < NL; l++) {
        // S0: wires 0-3 (lowest local bit first; pre-chain gates commute)
        {
            G2 G3 = load_gate(gsm4, l, 3);  gate_on_bit(G3, r, 0);
            G2 Gc = load_gate(gsm4, l, 2);  gate_on_bit(Gc, r, 1);
            G2 G1 = load_gate(gsm4, l, 1);  gate_on_bit(G1, r, 2);
            G2 G0 = load_gate(gsm4, l, 0);  gate_on_bit(G0, r, 3);
            cnot_loc(r, 3, 2); cnot_loc(r, 2, 1); cnot_loc(r, 1, 0);
        }
        XPOSE(st0, gS0, gS1, 0);
        // S1: wires 3..6; gates 4,5,6
        {
            G2 G6 = load_gate(gsm4, l, 6); gate_on_bit(G6, r, 0);
            G2 G5 = load_gate(gsm4, l, 5); gate_on_bit(G5, r, 1);
            G2 G4 = load_gate(gsm4, l, 4); gate_on_bit(G4, r, 2);
            cnot_loc(r, 3, 2); cnot_loc(r, 2, 1); cnot_loc(r, 1, 0);
        }
        XPOSE_W(st1, gS1, gS2, 0xC);
        // S2: wires 6..9; gates 7,8,9
        {
            G2 G9 = load_gate(gsm4, l, 9); gate_on_bit(G9, r, 0);
            G2 G8 = load_gate(gsm4, l, 8); gate_on_bit(G8, r, 1);
            G2 G7 = load_gate(gsm4, l, 7); gate_on_bit(G7, r, 2);
            cnot_loc(r, 3, 2); cnot_loc(r, 2, 1); cnot_loc(r, 1, 0);
        }
        XPOSE_W(st0, gS2, gS3, 0xF);
        // S3: gates 10,11 + CNOTs — only for the middle layer; last layer is
        // absorbed into the Q-form readout (operator back-propagation).
        if (l < NL - 1) {
            G2 Gb = load_gate(gsm4, l, 11); gate_on_bit(Gb, r, 0);
            G2 Ga = load_gate(gsm4, l, 10); gate_on_bit(Ga, r, 1);
            cnot_loc(r, 2, 1); cnot_loc(r, 1, 0);
            XPOSE(st1, gS3, gS0, 0xF);
        }
    }

    // --- Readout in S3 layout: wires 8(l3),9(l2),10(l1),11(l0) ---
    float swt = swtab[t];                      // sign-sum over wires 0..7
    float w8 = head_w[8], w9 = head_w[9];
    float acc = 0.f;
    #pragma unroll
    for (int g2 = 0; g2 < 4; g2++) {
        int l3 = g2 >> 1, l2 = g2 & 1;
        float2 z0 = r[g2 * 4 + 0], z1 = r[g2 * 4 + 1];
        float2 z2 = r[g2 * 4 + 2], z3 = r[g2 * 4 + 3];
        float P0 = z0.x*z0.x + z0.y*z0.y;
        float P1 = z1.x*z1.x + z1.y*z1.y;
        float P2 = z2.x*z2.x + z2.y*z2.y;
        float P3 = z3.x*z3.x + z3.y*z3.y;
        float A9 = swt + (l3 ? -w8 : w8) + (l2 ? -w9 : w9);
        float q = qsm[0]*P0 + qsm[1]*P1 + qsm[2]*P2 + qsm[3]*P3;
        float X, Y;
        X = z0.x*z1.x + z0.y*z1.y;  Y = z0.x*z1.y - z0.y*z1.x;  q += qsm[4]*X  - qsm[5]*Y;
        X = z0.x*z2.x + z0.y*z2.y;  Y = z0.x*z2.y - z0.y*z2.x;  q += qsm[6]*X  - qsm[7]*Y;
        X = z0.x*z3.x + z0.y*z3.y;  Y = z0.x*z3.y - z0.y*z3.x;  q += qsm[8]*X  - qsm[9]*Y;
        X = z1.x*z2.x + z1.y*z2.y;  Y = z1.x*z2.y - z1.y*z2.x;  q += qsm[10]*X - qsm[11]*Y;
        X = z1.x*z3.x + z1.y*z3.y;  Y = z1.x*z3.y - z1.y*z3.x;  q += qsm[12]*X - qsm[13]*Y;
        X = z2.x*z3.x + z2.y*z3.y;  Y = z2.x*z3.y - z2.y*z3.x;  q += qsm[14]*X - qsm[15]*Y;
        float sumP = (P0 + P1) + (P2 + P3);
        acc = fmaf(sumP, A9, acc);
        acc += l2 ? -q : q;
    }
    #pragma unroll
    for (int o = 16; o > 0; o >>= 1) acc += __shfl_xor_sync(0xFFFFFFFFu, acc, o);
    if ((t & 31) == 0) wred[t >> 5] = acc;
    __syncthreads();
    if (t == 0) {
        float tot = 0.f;
        #pragma unroll
        for (int i = 0; i < TPB / 32; i++) tot += wred[i];
        out[b] = tot + head_b[0];
    }
}

#define DYN_SMEM (2 * NS * sizeof(float2))

extern "C" void kernel_launch(void* const* d_in, const int* in_sizes, int n_in,
                              void* d_out, int out_size) {
    const float* x      = (const float*)d_in[0];
    const float* params = (const float*)d_in[1];
    const float* head_w = (const float*)d_in[2];
    const float* head_b = (const float*)d_in[3];
    float* out = (float*)d_out;
    int B = in_sizes[0] / NQ;
    static int smem_set = 0;
    if (!smem_set) {
        cudaFuncSetAttribute(qsim, cudaFuncAttributeMaxDynamicSharedMemorySize, DYN_SMEM);
        smem_set = 1;
    }
    prep_gates<<<1, 256>>>(params, head_w);
    qsim<<<B, TPB, DYN_SMEM>>>(x, head_w, head_b, out);
}

// round 13
// speedup vs baseline: 1.0543x; 1.0044x over previous
#include <cuda_runtime.h>

#define NQ 12
#define NS 4096
#define TPB 256
#define NL 3

__device__ float g_gates[NL * NQ * 8];
__device__ float g_Q[16];

__constant__ float4 c_gates4[NL * NQ * 2];   // gates via constant port
__constant__ float  c_Q[16];                 // readout Hermitian form

__global__ void prep_gates(const float* __restrict__ params, const float* __restrict__ head_w) {
    int t = blockIdx.x * blockDim.x + threadIdx.x;
    if (t < NL * NQ) {
        float t0 = params[t * 3 + 0], t1 = params[t * 3 + 1], t2 = params[t * 3 + 2];
        float c0 = cosf(0.5f * t0), s0 = sinf(0.5f * t0);
        float cp = cosf(0.5f * t1), sp = sinf(0.5f * t1);
        float c2 = cosf(0.5f * t2), s2 = sinf(0.5f * t2);
        float A_re = cp * c0, A_im = -sp * c0;
        float B_re = -cp * s0, B_im = sp * s0;
        float C_re = cp * s0, C_im = sp * s0;
        float D_re = cp * c0, D_im = sp * c0;
        float* g = &g_gates[t * 8];
        g[0] = c2 * A_re - s2 * C_re;  g[1] = c2 * A_im - s2 * C_im;
        g[2] = c2 * B_re - s2 * D_re;  g[3] = c2 * B_im - s2 * D_im;
        g[4] = s2 * A_re + c2 * C_re;  g[5] = s2 * A_im + c2 * C_im;
        g[6] = s2 * B_re + c2 * D_re;  g[7] = s2 * B_im + c2 * D_im;
    }
    __syncthreads();
    if (t == 0) {
        // H = G^dag Z G for last-layer gates 10, 11
        const float* ga = &g_gates[((NL - 1) * NQ + 10) * 8];
        const float* gb = &g_gates[((NL - 1) * NQ + 11) * 8];
        float A00 = ga[0]*ga[0] + ga[1]*ga[1] - (ga[4]*ga[4] + ga[5]*ga[5]);
        float A11 = ga[2]*ga[2] + ga[3]*ga[3] - (ga[6]*ga[6] + ga[7]*ga[7]);
        float A01x = ga[0]*ga[2] + ga[1]*ga[3] - (ga[4]*ga[6] + ga[5]*ga[7]);
        float A01y = ga[0]*ga[3] - ga[1]*ga[2] - (ga[4]*ga[7] - ga[5]*ga[6]);
        float B00 = gb[0]*gb[0] + gb[1]*gb[1] - (gb[4]*gb[4] + gb[5]*gb[5]);
        float B11 = gb[2]*gb[2] + gb[3]*gb[3] - (gb[6]*gb[6] + gb[7]*gb[7]);
        float B01x = gb[0]*gb[2] + gb[1]*gb[3] - (gb[4]*gb[6] + gb[5]*gb[7]);
        float B01y = gb[0]*gb[3] - gb[1]*gb[2] - (gb[4]*gb[7] - gb[5]*gb[6]);
        float w10 = head_w[10], w11 = head_w[11];
        float cA = w10 + w11 * B00;
        float cB = w10 + w11 * B11;
        g_Q[0] = A00 * cA;
        g_Q[1] = A00 * cB;
        g_Q[2] = A11 * cA;
        g_Q[3] = A11 * cB;
        g_Q[4] = 2.f * w11 * A00 * B01x;  g_Q[5] = 2.f * w11 * A00 * B01y;
        g_Q[6] = 2.f * A01x * cA;         g_Q[7] = 2.f * A01y * cA;
        g_Q[8]  = 2.f * w11 * (A01x*B01x - A01y*B01y);
        g_Q[9]  = 2.f * w11 * (A01x*B01y + A01y*B01x);
        g_Q[10] = 2.f * w11 * (A01x*B01x + A01y*B01y);
        g_Q[11] = 2.f * w11 * (A01y*B01x - A01x*B01y);
        g_Q[12] = 2.f * A01x * cB;        g_Q[13] = 2.f * A01y * cB;
        g_Q[14] = 2.f * w11 * A11 * B01x; g_Q[15] = 2.f * w11 * A11 * B01y;
    }
}

struct G2 { float2 g00, g01, g10, g11; };

__device__ __forceinline__ float2 cmul(float2 a, float2 b) {
    return make_float2(a.x * b.x - a.y * b.y, a.x * b.y + a.y * b.x);
}

__device__ __forceinline__ void apply_pair(const G2& g, float2& a, float2& b) {
    float2 na, nb;
    na.x = g.g00.x * a.x - g.g00.y * a.y + g.g01.x * b.x - g.g01.y * b.y;
    na.y = g.g00.x * a.y + g.g00.y * a.x + g.g01.x * b.y + g.g01.y * b.x;
    nb.x = g.g10.x * a.x - g.g10.y * a.y + g.g11.x * b.x - g.g11.y * b.y;
    nb.y = g.g10.x * a.y + g.g10.y * a.x + g.g11.x * b.y + g.g11.y * b.x;
    a = na; b = nb;
}

__device__ __forceinline__ G2 load_gate(int l, int w) {
    float4 p0 = c_gates4[(l * NQ + w) * 2 + 0];
    float4 p1 = c_gates4[(l * NQ + w) * 2 + 1];
    G2 r;
    r.g00 = make_float2(p0.x, p0.y);
    r.g01 = make_float2(p0.z, p0.w);
    r.g10 = make_float2(p1.x, p1.y);
    r.g11 = make_float2(p1.z, p1.w);
    return r;
}

__device__ __forceinline__ void gate_on_bit(const G2& g, float2 r[16], int k) {
    #pragma unroll
    for (int l = 0; l < 16; l++)
        if (!(l & (1 << k))) apply_pair(g, r[l], r[l | (1 << k)]);
}

__device__ __forceinline__ void cnot_loc(float2 r[16], int c, int tg) {
    #pragma unroll
    for (int l = 0; l < 16; l++)
        if ((l & (1 << c)) && !(l & (1 << tg))) {
            float2 tmp = r[l]; r[l] = r[l | (1 << tg)]; r[l | (1 << tg)] = tmp;
        }
}

// Stage maps (verified). t = thread (8 bits), l = local (4 bits).
__device__ __forceinline__ int gS0(int t, int l) { return (l << 8) | t; }
__device__ __forceinline__ int gS1(int t, int l) { return ((t >> 5) << 9) | (l << 5) | (t & 31); }
__device__ __forceinline__ int gS2(int t, int l) { return ((t >> 5) << 9) | (((t >> 2) & 7) << 6) | (l << 2) | (t & 3); }
__device__ __forceinline__ int gS3(int t, int l) { return ((t >> 5) << 9) | ((t & 31) << 4) | l; }
__device__ __forceinline__ int swz(int g, int m) { return g ^ ((g >> 4) & m); }

__global__ __launch_bounds__(TPB, 3) void qsim(
    const float* __restrict__ x, const float* __restrict__ head_w,
    const float* __restrict__ head_b, float* __restrict__ out) {
    extern __shared__ float2 stbuf[];          // 2 * 4096 float2 = 64 KB (double buffer)
    float2* st0 = stbuf;
    float2* st1 = stbuf + NS;
    __shared__ float2 vsm[NQ][2];
    __shared__ float wred[TPB / 32];

    int b = blockIdx.x, t = threadIdx.x;

    if (t < NQ) {
        // v_w = G_{layer0,w} @ [cos(x/2), -i sin(x/2)]
        float xv = x[b * NQ + t];
        float c = cosf(0.5f * xv), s = sinf(0.5f * xv);
        const float* g = (const float*)&c_gates4[t * 2];   // layer 0, wire t
        vsm[t][0] = make_float2(g[0] * c + s * g[3], g[1] * c - s * g[2]);
        vsm[t][1] = make_float2(g[4] * c + s * g[7], g[5] * c - s * g[6]);
    }
    __syncthreads();

    float2 r[16];

    // --- Init in S0 layout, layer-1 gates + CNOT chain absorbed ---
    {
        int u = t ^ (t >> 1);
        float2 P = vsm[5][(u >> 6) & 1];
        #pragma unroll
        for (int w = 6; w < NQ; w++) P = cmul(P, vsm[w][(u >> (11 - w)) & 1]);
        int t7 = (t >> 7) & 1;
        float2 W34[4];
        #pragma unroll
        for (int j = 0; j < 4; j++) {
            int l1 = j >> 1, l0 = j & 1;
            W34[j] = cmul(cmul(vsm[3][l1 ^ l0], vsm[4][t7 ^ l0]), P);
        }
        float2 W012[8];
        #pragma unroll
        for (int k = 0; k < 8; k++) {
            int l3 = k >> 2, l2 = (k >> 1) & 1, l1 = k & 1;
            W012[k] = cmul(cmul(vsm[0][l3], vsm[1][l3 ^ l2]), vsm[2][l2 ^ l1]);
        }
        #pragma unroll
        for (int l = 0; l < 16; l++)
            r[l] = cmul(W012[l >> 1], W34[l & 3]);
    }

    #define XPOSE(BUF, GSRC, GDST, MASK) do {                               \
        _Pragma("unroll")                                                   \
        for (int i_ = 0; i_ < 16; i_++) BUF[swz(GSRC(t, i_), MASK)] = r[i_]; \
        __syncthreads();                                                    \
        _Pragma("unroll")                                                   \
        for (int i_ = 0; i_ < 16; i_++) r[i_] = BUF[swz(GDST(t, i_), MASK)]; \
    } while (0)

    #define XPOSE_W(BUF, GSRC, GDST, MASK) do {                             \
        _Pragma("unroll")                                                   \
        for (int i_ = 0; i_ < 16; i_++) BUF[swz(GSRC(t, i_), MASK)] = r[i_]; \
        __syncwarp();                                                       \
        _Pragma("unroll")                                                   \
        for (int i_ = 0; i_ < 16; i_++) r[i_] = BUF[swz(GDST(t, i_), MASK)]; \
    } while (0)

    #pragma unroll
    for (int l = 1; l < NL; l++) {
        // S0: wires 0-3 (lowest local bit first; pre-chain gates commute)
        {
            G2 G3 = load_gate(l, 3);  gate_on_bit(G3, r, 0);
            G2 Gc = load_gate(l, 2);  gate_on_bit(Gc, r, 1);
            G2 G1 = load_gate(l, 1);  gate_on_bit(G1, r, 2);
            G2 G0 = load_gate(l, 0);  gate_on_bit(G0, r, 3);
            cnot_loc(r, 3, 2); cnot_loc(r, 2, 1); cnot_loc(r, 1, 0);
        }
        XPOSE(st0, gS0, gS1, 0);
        // S1: wires 3..6; gates 4,5,6
        {
            G2 G6 = load_gate(l, 6); gate_on_bit(G6, r, 0);
            G2 G5 = load_gate(l, 5); gate_on_bit(G5, r, 1);
            G2 G4 = load_gate(l, 4); gate_on_bit(G4, r, 2);
            cnot_loc(r, 3, 2); cnot_loc(r, 2, 1); cnot_loc(r, 1, 0);
        }
        XPOSE_W(st1, gS1, gS2, 0xC);
        // S2: wires 6..9; gates 7,8,9
        {
            G2 G9 = load_gate(l, 9); gate_on_bit(G9, r, 0);
            G2 G8 = load_gate(l, 8); gate_on_bit(G8, r, 1);
            G2 G7 = load_gate(l, 7); gate_on_bit(G7, r, 2);
            cnot_loc(r, 3, 2); cnot_loc(r, 2, 1); cnot_loc(r, 1, 0);
        }
        XPOSE_W(st0, gS2, gS3, 0xF);
        // S3: gates 10,11 + CNOTs — only for the middle layer; last layer is
        // absorbed into the Q-form readout (operator back-propagation).
        if (l < NL - 1) {
            G2 Gb = load_gate(l, 11); gate_on_bit(Gb, r, 0);
            G2 Ga = load_gate(l, 10); gate_on_bit(Ga, r, 1);
            cnot_loc(r, 2, 1); cnot_loc(r, 1, 0);
            XPOSE(st1, gS3, gS0, 0xF);
        }
    }

    // --- Readout in S3 layout: wires 8(l3),9(l2),10(l1),11(l0) ---
    float swt = 0.f;
    {
        int g = gS3(t, 0);
        #pragma unroll
        for (int w = 0; w < 8; w++)
            swt += ((g >> (11 - w)) & 1) ? -head_w[w] : head_w[w];
    }
    float w8 = head_w[8], w9 = head_w[9];
    float acc = 0.f;
    #pragma unroll
    for (int g2 = 0; g2 < 4; g2++) {
        int l3 = g2 >> 1, l2 = g2 & 1;
        float2 z0 = r[g2 * 4 + 0], z1 = r[g2 * 4 + 1];
        float2 z2 = r[g2 * 4 + 2], z3 = r[g2 * 4 + 3];
        float P0 = z0.x*z0.x + z0.y*z0.y;
        float P1 = z1.x*z1.x + z1.y*z1.y;
        float P2 = z2.x*z2.x + z2.y*z2.y;
        float P3 = z3.x*z3.x + z3.y*z3.y;
        float A9 = swt + (l3 ? -w8 : w8) + (l2 ? -w9 : w9);
        float q = c_Q[0]*P0 + c_Q[1]*P1 + c_Q[2]*P2 + c_Q[3]*P3;
        float X, Y;
        X = z0.x*z1.x + z0.y*z1.y;  Y = z0.x*z1.y - z0.y*z1.x;  q += c_Q[4]*X  - c_Q[5]*Y;
        X = z0.x*z2.x + z0.y*z2.y;  Y = z0.x*z2.y - z0.y*z2.x;  q += c_Q[6]*X  - c_Q[7]*Y;
        X = z0.x*z3.x + z0.y*z3.y;  Y = z0.x*z3.y - z0.y*z3.x;  q += c_Q[8]*X  - c_Q[9]*Y;
        X = z1.x*z2.x + z1.y*z2.y;  Y = z1.x*z2.y - z1.y*z2.x;  q += c_Q[10]*X - c_Q[11]*Y;
        X = z1.x*z3.x + z1.y*z3.y;  Y = z1.x*z3.y - z1.y*z3.x;  q += c_Q[12]*X - c_Q[13]*Y;
        X = z2.x*z3.x + z2.y*z3.y;  Y = z2.x*z3.y - z2.y*z3.x;  q += c_Q[14]*X - c_Q[15]*Y;
        float sumP = (P0 + P1) + (P2 + P3);
        acc = fmaf(sumP, A9, acc);
        acc += l2 ? -q : q;
    }
    #pragma unroll
    for (int o = 16; o > 0; o >>= 1) acc += __shfl_xor_sync(0xFFFFFFFFu, acc, o);
    if ((t & 31) == 0) wred[t >> 5] = acc;
    __syncthreads();
    if (t == 0) {
        float tot = 0.f;
        #pragma unroll
        for (int i = 0; i < TPB / 32; i++) tot += wred[i];
        out[b] = tot + head_b[0];
    }
}

#define DYN_SMEM (2 * NS * sizeof(float2))

extern "C" void kernel_launch(void* const* d_in, const int* in_sizes, int n_in,
                              void* d_out, int out_size) {
    const float* x      = (const float*)d_in[0];
    const float* params = (const float*)d_in[1];
    const float* head_w = (const float*)d_in[2];
    const float* head_b = (const float*)d_in[3];
    float* out = (float*)d_out;
    int B = in_sizes[0] / NQ;
    static int init_done = 0;
    static void* gaddr = 0;
    static void* qaddr = 0;
    if (!init_done) {
        cudaFuncSetAttribute(qsim, cudaFuncAttributeMaxDynamicSharedMemorySize, DYN_SMEM);
        cudaGetSymbolAddress(&gaddr, g_gates);
        cudaGetSymbolAddress(&qaddr, g_Q);
        init_done = 1;
    }
    prep_gates<<<1, 64>>>(params, head_w);
    // D2D async copies into __constant__ (graph-capturable memcpy nodes)
    cudaMemcpyToSymbolAsync(c_gates4, gaddr, sizeof(float) * NL * NQ * 8, 0,
                            cudaMemcpyDeviceToDevice, 0);
    cudaMemcpyToSymbolAsync(c_Q, qaddr, sizeof(float) * 16, 0,
                            cudaMemcpyDeviceToDevice, 0);
    qsim<<<B, TPB, DYN_SMEM>>>(x, head_w, head_b, out);
}

// round 15
// speedup vs baseline: 1.0618x; 1.0071x over previous
#include <cuda_runtime.h>

#define NQ 12
#define NS 4096
#define TPB 256
#define NL 3

// One consolidated constant region: [0:288) gates, [288:304) Q, [304:316) head_w
#define OFF_Q  288
#define OFF_W  304
#define ALLSZ  320

__device__ __align__(16) float g_all[ALLSZ];
__constant__ __align__(16) float c_all[ALLSZ];

__global__ void prep_gates(const float* __restrict__ params, const float* __restrict__ head_w) {
    int t = blockIdx.x * blockDim.x + threadIdx.x;
    if (t < NL * NQ) {
        float t0 = params[t * 3 + 0], t1 = params[t * 3 + 1], t2 = params[t * 3 + 2];
        float c0 = cosf(0.5f * t0), s0 = sinf(0.5f * t0);
        float cp = cosf(0.5f * t1), sp = sinf(0.5f * t1);
        float c2 = cosf(0.5f * t2), s2 = sinf(0.5f * t2);
        float A_re = cp * c0, A_im = -sp * c0;
        float B_re = -cp * s0, B_im = sp * s0;
        float C_re = cp * s0, C_im = sp * s0;
        float D_re = cp * c0, D_im = sp * c0;
        float* g = &g_all[t * 8];
        g[0] = c2 * A_re - s2 * C_re;  g[1] = c2 * A_im - s2 * C_im;
        g[2] = c2 * B_re - s2 * D_re;  g[3] = c2 * B_im - s2 * D_im;
        g[4] = s2 * A_re + c2 * C_re;  g[5] = s2 * A_im + c2 * C_im;
        g[6] = s2 * B_re + c2 * D_re;  g[7] = s2 * B_im + c2 * D_im;
    }
    if (t < NQ) g_all[OFF_W + t] = head_w[t];
    __syncthreads();
    if (t == 0) {
        // H = G^dag Z G for last-layer gates 10, 11
        const float* ga = &g_all[((NL - 1) * NQ + 10) * 8];
        const float* gb = &g_all[((NL - 1) * NQ + 11) * 8];
        float A00 = ga[0]*ga[0] + ga[1]*ga[1] - (ga[4]*ga[4] + ga[5]*ga[5]);
        float A11 = ga[2]*ga[2] + ga[3]*ga[3] - (ga[6]*ga[6] + ga[7]*ga[7]);
        float A01x = ga[0]*ga[2] + ga[1]*ga[3] - (ga[4]*ga[6] + ga[5]*ga[7]);
        float A01y = ga[0]*ga[3] - ga[1]*ga[2] - (ga[4]*ga[7] - ga[5]*ga[6]);
        float B00 = gb[0]*gb[0] + gb[1]*gb[1] - (gb[4]*gb[4] + gb[5]*gb[5]);
        float B11 = gb[2]*gb[2] + gb[3]*gb[3] - (gb[6]*gb[6] + gb[7]*gb[7]);
        float B01x = gb[0]*gb[2] + gb[1]*gb[3] - (gb[4]*gb[6] + gb[5]*gb[7]);
        float B01y = gb[0]*gb[3] - gb[1]*gb[2] - (gb[4]*gb[7] - gb[5]*gb[6]);
        float w10 = head_w[10], w11 = head_w[11];
        float cA = w10 + w11 * B00;
        float cB = w10 + w11 * B11;
        float* Q = &g_all[OFF_Q];
        Q[0] = A00 * cA;
        Q[1] = A00 * cB;
        Q[2] = A11 * cA;
        Q[3] = A11 * cB;
        Q[4] = 2.f * w11 * A00 * B01x;  Q[5] = 2.f * w11 * A00 * B01y;
        Q[6] = 2.f * A01x * cA;         Q[7] = 2.f * A01y * cA;
        Q[8]  = 2.f * w11 * (A01x*B01x - A01y*B01y);
        Q[9]  = 2.f * w11 * (A01x*B01y + A01y*B01x);
        Q[10] = 2.f * w11 * (A01x*B01x + A01y*B01y);
        Q[11] = 2.f * w11 * (A01y*B01x - A01x*B01y);
        Q[12] = 2.f * A01x * cB;        Q[13] = 2.f * A01y * cB;
        Q[14] = 2.f * w11 * A11 * B01x; Q[15] = 2.f * w11 * A11 * B01y;
    }
}

struct G2 { float2 g00, g01, g10, g11; };

__device__ __forceinline__ float2 cmul(float2 a, float2 b) {
    return make_float2(a.x * b.x - a.y * b.y, a.x * b.y + a.y * b.x);
}

__device__ __forceinline__ void apply_pair(const G2& g, float2& a, float2& b) {
    float2 na, nb;
    na.x = g.g00.x * a.x - g.g00.y * a.y + g.g01.x * b.x - g.g01.y * b.y;
    na.y = g.g00.x * a.y + g.g00.y * a.x + g.g01.x * b.y + g.g01.y * b.x;
    nb.x = g.g10.x * a.x - g.g10.y * a.y + g.g11.x * b.x - g.g11.y * b.y;
    nb.y = g.g10.x * a.y + g.g10.y * a.x + g.g11.x * b.y + g.g11.y * b.x;
    a = na; b = nb;
}

__device__ __forceinline__ G2 load_gate(int l, int w) {
    const float4* g4 = (const float4*)c_all;
    float4 p0 = g4[(l * NQ + w) * 2 + 0];
    float4 p1 = g4[(l * NQ + w) * 2 + 1];
    G2 r;
    r.g00 = make_float2(p0.x, p0.y);
    r.g01 = make_float2(p0.z, p0.w);
    r.g10 = make_float2(p1.x, p1.y);
    r.g11 = make_float2(p1.z, p1.w);
    return r;
}

__device__ __forceinline__ void gate_on_bit(const G2& g, float2 r[16], int k) {
    #pragma unroll
    for (int l = 0; l < 16; l++)
        if (!(l & (1 << k))) apply_pair(g, r[l], r[l | (1 << k)]);
}

__device__ __forceinline__ void cnot_loc(float2 r[16], int c, int tg) {
    #pragma unroll
    for (int l = 0; l < 16; l++)
        if ((l & (1 << c)) && !(l & (1 << tg))) {
            float2 tmp = r[l]; r[l] = r[l | (1 << tg)]; r[l | (1 << tg)] = tmp;
        }
}

// Stage maps (verified). t = thread (8 bits), l = local (4 bits).
__device__ __forceinline__ int gS0(int t, int l) { return (l << 8) | t; }
__device__ __forceinline__ int gS1(int t, int l) { return ((t >> 5) << 9) | (l << 5) | (t & 31); }
__device__ __forceinline__ int gS2(int t, int l) { return ((t >> 5) << 9) | (((t >> 2) & 7) << 6) | (l << 2) | (t & 3); }
__device__ __forceinline__ int gS3(int t, int l) { return ((t >> 5) << 9) | ((t & 31) << 4) | l; }
__device__ __forceinline__ int swz(int g, int m) { return g ^ ((g >> 4) & m); }

__global__ __launch_bounds__(TPB, 3) void qsim(
    const float* __restrict__ x, const float* __restrict__ head_w,
    const float* __restrict__ head_b, float* __restrict__ out) {
    extern __shared__ float2 stbuf[];          // 2 * 4096 float2 = 64 KB (double buffer)
    float2* st0 = stbuf;
    float2* st1 = stbuf + NS;
    __shared__ float2 vsm[NQ][2];
    __shared__ float wred[TPB / 32];

    int b = blockIdx.x, t = threadIdx.x;

    if (t < NQ) {
        // v_w = G_{layer0,w} @ [cos(x/2), -i sin(x/2)]
        float xv = x[b * NQ + t];
        float c = cosf(0.5f * xv), s = sinf(0.5f * xv);
        const float* g = &c_all[t * 8];        // layer 0, wire t
        vsm[t][0] = make_float2(g[0] * c + s * g[3], g[1] * c - s * g[2]);
        vsm[t][1] = make_float2(g[4] * c + s * g[7], g[5] * c - s * g[6]);
    }
    __syncthreads();

    float2 r[16];

    // --- Init in S0 layout, layer-1 gates + CNOT chain absorbed ---
    {
        int u = t ^ (t >> 1);
        float2 P = vsm[5][(u >> 6) & 1];
        #pragma unroll
        for (int w = 6; w < NQ; w++) P = cmul(P, vsm[w][(u >> (11 - w)) & 1]);
        int t7 = (t >> 7) & 1;
        float2 W34[4];
        #pragma unroll
        for (int j = 0; j < 4; j++) {
            int l1 = j >> 1, l0 = j & 1;
            W34[j] = cmul(cmul(vsm[3][l1 ^ l0], vsm[4][t7 ^ l0]), P);
        }
        float2 W012[8];
        #pragma unroll
        for (int k = 0; k < 8; k++) {
            int l3 = k >> 2, l2 = (k >> 1) & 1, l1 = k & 1;
            W012[k] = cmul(cmul(vsm[0][l3], vsm[1][l3 ^ l2]), vsm[2][l2 ^ l1]);
        }
        #pragma unroll
        for (int l = 0; l < 16; l++)
            r[l] = cmul(W012[l >> 1], W34[l & 3]);
    }

    #define XPOSE(BUF, GSRC, GDST, MASK) do {                               \
        _Pragma("unroll")                                                   \
        for (int i_ = 0; i_ < 16; i_++) BUF[swz(GSRC(t, i_), MASK)] = r[i_]; \
        __syncthreads();                                                    \
        _Pragma("unroll")                                                   \
        for (int i_ = 0; i_ < 16; i_++) r[i_] = BUF[swz(GDST(t, i_), MASK)]; \
    } while (0)

    #define XPOSE_W(BUF, GSRC, GDST, MASK) do {                             \
        _Pragma("unroll")                                                   \
        for (int i_ = 0; i_ < 16; i_++) BUF[swz(GSRC(t, i_), MASK)] = r[i_]; \
        __syncwarp();                                                       \
        _Pragma("unroll")                                                   \
        for (int i_ = 0; i_ < 16; i_++) r[i_] = BUF[swz(GDST(t, i_), MASK)]; \
    } while (0)

    #pragma unroll
    for (int l = 1; l < NL; l++) {
        // S0: wires 0-3 (lowest local bit first; pre-chain gates commute)
        {
            G2 G3 = load_gate(l, 3);  gate_on_bit(G3, r, 0);
            G2 Gc = load_gate(l, 2);  gate_on_bit(Gc, r, 1);
            G2 G1 = load_gate(l, 1);  gate_on_bit(G1, r, 2);
            G2 G0 = load_gate(l, 0);  gate_on_bit(G0, r, 3);
            cnot_loc(r, 3, 2); cnot_loc(r, 2, 1); cnot_loc(r, 1, 0);
        }
        XPOSE(st0, gS0, gS1, 0);
        // S1: wires 3..6; gates 4,5,6
        {
            G2 G6 = load_gate(l, 6); gate_on_bit(G6, r, 0);
            G2 G5 = load_gate(l, 5); gate_on_bit(G5, r, 1);
            G2 G4 = load_gate(l, 4); gate_on_bit(G4, r, 2);
            cnot_loc(r, 3, 2); cnot_loc(r, 2, 1); cnot_loc(r, 1, 0);
        }
        XPOSE_W(st1, gS1, gS2, 0xC);
        // S2: wires 6..9; gates 7,8,9
        {
            G2 G9 = load_gate(l, 9); gate_on_bit(G9, r, 0);
            G2 G8 = load_gate(l, 8); gate_on_bit(G8, r, 1);
            G2 G7 = load_gate(l, 7); gate_on_bit(G7, r, 2);
            cnot_loc(r, 3, 2); cnot_loc(r, 2, 1); cnot_loc(r, 1, 0);
        }
        XPOSE_W(st0, gS2, gS3, 0xF);
        // S3: gates 10,11 + CNOTs — only for the middle layer; last layer is
        // absorbed into the Q-form readout (operator back-propagation).
        if (l < NL - 1) {
            G2 Gb = load_gate(l, 11); gate_on_bit(Gb, r, 0);
            G2 Ga = load_gate(l, 10); gate_on_bit(Ga, r, 1);
            cnot_loc(r, 2, 1); cnot_loc(r, 1, 0);
            XPOSE(st1, gS3, gS0, 0xF);
        }
    }

    // --- Readout in S3 layout: wires 8(l3),9(l2),10(l1),11(l0) ---
    // All coefficients via the constant port (LDC) — no LDG in the hot path.
    float swt = 0.f;
    {
        int g = gS3(t, 0);
        #pragma unroll
        for (int w = 0; w < 8; w++)
            swt += ((g >> (11 - w)) & 1) ? -c_all[OFF_W + w] : c_all[OFF_W + w];
    }
    float w8 = c_all[OFF_W + 8], w9 = c_all[OFF_W + 9];
    const float* Q = &c_all[OFF_Q];
    float acc = 0.f;
    #pragma unroll
    for (int g2 = 0; g2 < 4; g2++) {
        int l3 = g2 >> 1, l2 = g2 & 1;
        float2 z0 = r[g2 * 4 + 0], z1 = r[g2 * 4 + 1];
        float2 z2 = r[g2 * 4 + 2], z3 = r[g2 * 4 + 3];
        float P0 = z0.x*z0.x + z0.y*z0.y;
        float P1 = z1.x*z1.x + z1.y*z1.y;
        float P2 = z2.x*z2.x + z2.y*z2.y;
        float P3 = z3.x*z3.x + z3.y*z3.y;
        float A9 = swt + (l3 ? -w8 : w8) + (l2 ? -w9 : w9);
        float q = Q[0]*P0 + Q[1]*P1 + Q[2]*P2 + Q[3]*P3;
        float X, Y;
        X = z0.x*z1.x + z0.y*z1.y;  Y = z0.x*z1.y - z0.y*z1.x;  q += Q[4]*X  - Q[5]*Y;
        X = z0.x*z2.x + z0.y*z2.y;  Y = z0.x*z2.y - z0.y*z2.x;  q += Q[6]*X  - Q[7]*Y;
        X = z0.x*z3.x + z0.y*z3.y;  Y = z0.x*z3.y - z0.y*z3.x;  q += Q[8]*X  - Q[9]*Y;
        X = z1.x*z2.x + z1.y*z2.y;  Y = z1.x*z2.y - z1.y*z2.x;  q += Q[10]*X - Q[11]*Y;
        X = z1.x*z3.x + z1.y*z3.y;  Y = z1.x*z3.y - z1.y*z3.x;  q += Q[12]*X - Q[13]*Y;
        X = z2.x*z3.x + z2.y*z3.y;  Y = z2.x*z3.y - z2.y*z3.x;  q += Q[14]*X - Q[15]*Y;
        float sumP = (P0 + P1) + (P2 + P3);
        acc = fmaf(sumP, A9, acc);
        acc += l2 ? -q : q;
    }
    #pragma unroll
    for (int o = 16; o > 0; o >>= 1) acc += __shfl_xor_sync(0xFFFFFFFFu, acc, o);
    if ((t & 31) == 0) wred[t >> 5] = acc;
    __syncthreads();
    if (t == 0) {
        float tot = 0.f;
        #pragma unroll
        for (int i = 0; i < TPB / 32; i++) tot += wred[i];
        out[b] = tot + head_b[0];
    }
}

#define DYN_SMEM (2 * NS * sizeof(float2))

extern "C" void kernel_launch(void* const* d_in, const int* in_sizes, int n_in,
                              void* d_out, int out_size) {
    const float* x      = (const float*)d_in[0];
    const float* params = (const float*)d_in[1];
    const float* head_w = (const float*)d_in[2];
    const float* head_b = (const float*)d_in[3];
    float* out = (float*)d_out;
    int B = in_sizes[0] / NQ;
    static int init_done = 0;
    static void* gaddr = 0;
    if (!init_done) {
        cudaFuncSetAttribute(qsim, cudaFuncAttributeMaxDynamicSharedMemorySize, DYN_SMEM);
        cudaGetSymbolAddress(&gaddr, g_all);
        init_done = 1;
    }
    prep_gates<<<1, 64>>>(params, head_w);
    // ONE D2D memcpy node into __constant__ (graph-capturable)
    cudaMemcpyToSymbolAsync(c_all, gaddr, sizeof(float) * ALLSZ, 0,
                            cudaMemcpyDeviceToDevice, 0);
    qsim<<<B, TPB, DYN_SMEM>>>(x, head_w, head_b, out);
}